// round 16
// baseline (speedup 1.0000x reference)
#include <cuda_runtime.h>
#include <cuda_bf16.h>
#include <stdint.h>

// Problem constants
#define BSZ 8
#define SEQ 4096
#define HID 1024
#define NEXP 8
#define CAP 512
#define NTOK (BSZ * SEQ)           // 32768
#define NPAIR (BSZ * NEXP)         // 64
#define IDX_OFF 0
#define SCORE_OFF (NPAIR * CAP)    // 32768
#define MASK_OFF (2 * NPAIR * CAP) // 65536
#define MASK_FLOATS (NPAIR * CAP * SEQ)   // 134217728 floats = 512 MB

#define GATE_BLOCKS 4096           // 8 warps/block, 1 token/warp
#define ZF_PER_BLK  32768          // floats per zero-fill block (128 KB)
#define ZF_BLOCKS   4096           // all 512 MB of mask zeros in kernel A

#define SORT_BLOCKS 128            // 2 per pair, 2048 keys each

// Scratch (device globals; no allocation allowed)
__device__ float g_aff[NPAIR * SEQ];                  // affinity [b*8+e][s]
__device__ unsigned long long g_runs[NPAIR * 1024];   // 2 desc runs of 512 / pair

// ---------------------------------------------------------------------------
// Kernel A: gate + full mask zero-fill, interleaved 1:1 (even=gate, odd=ZF).
// Gate arithmetic FROZEN bit-exact since R9: lane L accumulates
// k = 4L + j + 128 i (j inner, i outer, single fp32 FMA chain), 32-lane
// xor-butterfly tree, exact max, fsub.rn, libdevice expf, sequential e-sum,
// __fdiv_rn. NEW mapping: 1 token/warp (8 acc regs) for high occupancy.
// ---------------------------------------------------------------------------
__global__ __launch_bounds__(256) void gate_zf_kernel(
    const float* __restrict__ hid, const float* __restrict__ w,
    float* __restrict__ out)
{
    __shared__ float ws[NEXP * HID];   // ws[e*1024 + k], e-major
    int tid = threadIdx.x;
    int grp = blockIdx.x >> 1;

    if (blockIdx.x & 1) {
        // ---- zero-fill path: block grp covers 128 KB of the mask ----
        float4* dst = (float4*)(out + (size_t)MASK_OFF + (size_t)grp * ZF_PER_BLK);
        float4 z = make_float4(0.f, 0.f, 0.f, 0.f);
#pragma unroll
        for (int q = tid; q < ZF_PER_BLK / 4; q += 256)
            dst[q] = z;
        return;
    }

    // ---- gate path (bit-exact, frozen sequence; 1 token per warp) ----
    for (int i = tid; i < HID * NEXP; i += 256) {
        int k = i >> 3, e = i & 7;
        ws[e * HID + k] = w[i];
    }
    __syncthreads();

    int warp = tid >> 5, lane = tid & 31;
    int tok = grp * 8 + warp;              // 0 .. 32767
    const float* h0 = hid + (size_t)tok * HID;

    float acc[8];
#pragma unroll
    for (int e = 0; e < 8; e++) acc[e] = 0.0f;

#pragma unroll
    for (int i = 0; i < 8; i++) {
        int kbase = i * 128 + lane * 4;
        float4 h4 = *(const float4*)(h0 + kbase);
        float hj[4] = {h4.x, h4.y, h4.z, h4.w};
#pragma unroll
        for (int e = 0; e < 8; e++) {
#pragma unroll
            for (int j = 0; j < 4; j++)
                acc[e] = __fmaf_rn(hj[j], ws[e * HID + kbase + j], acc[e]);
        }
    }

    // 32-lane tree combine (pairing frozen)
#pragma unroll
    for (int off = 16; off > 0; off >>= 1)
#pragma unroll
        for (int e = 0; e < 8; e++)
            acc[e] = __fadd_rn(acc[e], __shfl_xor_sync(0xFFFFFFFFu, acc[e], off));

    if (lane == 0) {
        int b = tok >> 12;
        int s = tok & (SEQ - 1);

        float m = acc[0];
#pragma unroll
        for (int e = 1; e < 8; e++) m = fmaxf(m, acc[e]);

        float ex[8];
        float sum = 0.0f;
#pragma unroll
        for (int e = 0; e < 8; e++) {
            float d = __fsub_rn(acc[e], m);
            ex[e] = expf(d);
            sum = __fadd_rn(sum, ex[e]);
        }
#pragma unroll
        for (int e = 0; e < 8; e++)
            g_aff[((size_t)(b * NEXP + e)) * SEQ + s] = __fdiv_rn(ex[e], sum);
    }
}

// ---------------------------------------------------------------------------
// Kernel B: per half-pair (2048 keys): sort 4 chunks of 512 descending, then
// bitonic top-k merge-selection 4 -> 2 -> 1; outputs ONE descending run of
// 512 = exact top-512 of the 2048 (distinct keys => identical to full-sort
// prefix). Key = (float_bits << 32) | ~index (desc value, asc index on ties).
// ---------------------------------------------------------------------------
__global__ __launch_bounds__(512) void chunksort_kernel(void)
{
    __shared__ unsigned long long keys[2048];
    int sort_id = blockIdx.x;              // 0..127
    int pair = sort_id >> 1;
    int half = sort_id & 1;
    int gbase = half * 2048;
    const float* a = g_aff + (size_t)pair * SEQ + gbase;
    int tid = threadIdx.x;

    for (int t = tid; t < 2048; t += 512) {
        unsigned int fb = __float_as_uint(a[t]);
        keys[t] = ((unsigned long long)fb << 32) | (unsigned int)(~(gbase + t));
    }
    __syncthreads();

    // Phase 1: sort each 512-chunk descending
    for (int k = 2; k <= 512; k <<= 1) {
        for (int j = k >> 1; j > 0; j >>= 1) {
#pragma unroll 2
            for (int c = tid; c < 1024; c += 512) {
                int t = ((c & ~(j - 1)) << 1) | (c & (j - 1));
                int txj = t | j;
                unsigned long long x = keys[t], y = keys[txj];
                bool desc = (((t & 511) & k) == 0);
                if (desc ? (x < y) : (x > y)) { keys[t] = y; keys[txj] = x; }
            }
            __syncthreads();
        }
    }

    // Phase 2: merge-select (0,1)->run@0, (2,3)->run@1024, then 9 desc stages
    for (int c = tid; c < 1024; c += 512) {
        int m = c >> 9, i = c & 511;
        int baseA = m * 1024, baseB = baseA + 512;
        unsigned long long x = keys[baseA + i], y = keys[baseB + (511 - i)];
        keys[baseA + i] = (x > y) ? x : y;
    }
    __syncthreads();
    for (int j = 256; j > 0; j >>= 1) {
        {
            int c = tid;
            int m = c >> 8, i = c & 255;
            int base = m * 1024;
            int t = base + (((i & ~(j - 1)) << 1) | (i & (j - 1)));
            int txj = t | j;
            unsigned long long x = keys[t], y = keys[txj];
            if (x < y) { keys[t] = y; keys[txj] = x; }
        }
        __syncthreads();
    }

    // Phase 3: merge-select (0, 1024) -> final top-512 @0, then 9 desc stages
    if (tid < 512) {
        unsigned long long x = keys[tid], y = keys[1024 + (511 - tid)];
        keys[tid] = (x > y) ? x : y;
    }
    __syncthreads();
    for (int j = 256; j > 0; j >>= 1) {
        if (tid < 256) {
            int t = ((tid & ~(j - 1)) << 1) | (tid & (j - 1));
            int txj = t | j;
            unsigned long long x = keys[t], y = keys[txj];
            if (x < y) { keys[t] = y; keys[txj] = x; }
        }
        __syncthreads();
    }

    unsigned long long* dst = g_runs + (size_t)pair * 1024 + half * 512;
    dst[tid] = keys[tid];
}

// ---------------------------------------------------------------------------
// Kernel C: per pair, merge-select the two 512-runs -> final top-512 desc,
// then fused epilogue (indices, scores, one-hot into pre-zeroed mask).
// ---------------------------------------------------------------------------
__global__ __launch_bounds__(512) void merge_epi_kernel(float* __restrict__ out)
{
    __shared__ unsigned long long keys[1024];
    int pair = blockIdx.x;
    int tid = threadIdx.x;
    const unsigned long long* src = g_runs + (size_t)pair * 1024;

    keys[tid] = src[tid];
    keys[tid + 512] = src[tid + 512];
    __syncthreads();

    unsigned long long x = keys[tid], y = keys[512 + (511 - tid)];
    keys[tid] = (x > y) ? x : y;
    __syncthreads();
    for (int j = 256; j > 0; j >>= 1) {
        if (tid < 256) {
            int t = ((tid & ~(j - 1)) << 1) | (tid & (j - 1));
            int txj = t | j;
            unsigned long long a = keys[t], b = keys[txj];
            if (a < b) { keys[t] = b; keys[txj] = a; }
        }
        __syncthreads();
    }

    unsigned long long key = keys[tid];
    int   si = (int)(~(unsigned int)key);
    float v  = __uint_as_float((unsigned int)(key >> 32));
    int row = pair * CAP + tid;
    out[IDX_OFF + row]   = (float)si;                 // topk_indices
    out[SCORE_OFF + row] = v;                         // topk_scores
    out[MASK_OFF + (size_t)row * SEQ + si] = 1.0f;    // one-hot
}

extern "C" void kernel_launch(void* const* d_in, const int* in_sizes, int n_in,
                              void* d_out, int out_size)
{
    const float* hid = (const float*)d_in[0];   // [8, 4096, 1024] fp32
    const float* w   = (const float*)d_in[1];   // [1024, 8] fp32
    float* out = (float*)d_out;

    gate_zf_kernel<<<GATE_BLOCKS + ZF_BLOCKS, 256>>>(hid, w, out);  // 8192
    chunksort_kernel<<<SORT_BLOCKS, 512>>>();                        // 128
    merge_epi_kernel<<<NPAIR, 512>>>(out);                           // 64
}

// round 17
// speedup vs baseline: 1.0906x; 1.0906x over previous
#include <cuda_runtime.h>
#include <cuda_bf16.h>
#include <stdint.h>

// Problem constants
#define BSZ 8
#define SEQ 4096
#define HID 1024
#define NEXP 8
#define CAP 512
#define NTOK (BSZ * SEQ)           // 32768
#define NPAIR (BSZ * NEXP)         // 64
#define IDX_OFF 0
#define SCORE_OFF (NPAIR * CAP)    // 32768
#define MASK_OFF (2 * NPAIR * CAP) // 65536
#define MASK_FLOATS (NPAIR * CAP * SEQ)   // 134217728 floats = 512 MB

#define GATE_BLOCKS 2048           // 8 warps/block, 2 tokens/warp
#define ZF_PER_BLK  32768          // floats per zero-fill block (128 KB)
#define ZF_BLOCKS   4096           // all 512 MB of mask zeros in kernel A

#define SORT_BLOCKS 128            // 2 per pair, 2048 keys each

// Scratch (device globals; no allocation allowed)
__device__ float g_aff[NPAIR * SEQ];                  // affinity [b*8+e][s]
__device__ unsigned long long g_runs[NPAIR * 1024];   // 2 desc runs of 512 / pair

// ---------------------------------------------------------------------------
// Kernel A: gate (blocks [0,2048)) + full mask zero-fill (blocks [2048,+4096)).
// Gate arithmetic FROZEN bit-exact since R9: per (token,expert) chain is
// k = 4L + j + 128 i (i ascending, j inner, single fp32 FMA accumulator),
// 32-lane xor-butterfly combine, exact max, fsub.rn, libdevice expf,
// sequential e-sum, __fdiv_rn.
// Mapping: 2 tokens/warp (LDS amortized 2x), w staged as conflict-free
// float4 LDS, e-loop split in halves to cap live registers (<=64, 4 CTA/SM).
// ---------------------------------------------------------------------------
__global__ __launch_bounds__(256, 4) void gate_zf_kernel(
    const float* __restrict__ hid, const float* __restrict__ w,
    float* __restrict__ out)
{
    __shared__ float ws[NEXP * HID];   // ws[e*1024 + k], e-major
    int tid = threadIdx.x;

    if (blockIdx.x >= GATE_BLOCKS) {
        int zf_id = blockIdx.x - GATE_BLOCKS;
        float4* dst = (float4*)(out + (size_t)MASK_OFF + (size_t)zf_id * ZF_PER_BLK);
        float4 z = make_float4(0.f, 0.f, 0.f, 0.f);
#pragma unroll
        for (int q = tid; q < ZF_PER_BLK / 4; q += 256)
            dst[q] = z;
        return;
    }

    // ---- gate path (bit-exact, frozen sequence) ----
    for (int i = tid; i < HID * NEXP; i += 256) {
        int k = i >> 3, e = i & 7;
        ws[e * HID + k] = w[i];
    }
    __syncthreads();

    int warp = tid >> 5, lane = tid & 31;
    int tok0 = (blockIdx.x * 8 + warp) * 2;    // 2 tokens per warp
    const float* h0 = hid + (size_t)tok0 * HID;
    const float4* ws4 = (const float4*)ws;     // ws4[e*256 + 32 i + L]

    float acc[2][8];
#pragma unroll
    for (int t = 0; t < 2; t++)
#pragma unroll
        for (int e = 0; e < 8; e++) acc[t][e] = 0.0f;

#pragma unroll
    for (int i = 0; i < 8; i++) {
        int kidx = i * 32 + lane;              // float4 index within e-row
        float4 h40 = *(const float4*)(h0 + (size_t)0 * HID + kidx * 4);
        float4 h41 = *(const float4*)(h0 + (size_t)1 * HID + kidx * 4);
        float hj0[4] = {h40.x, h40.y, h40.z, h40.w};
        float hj1[4] = {h41.x, h41.y, h41.z, h41.w};
#pragma unroll
        for (int eh = 0; eh < 2; eh++) {
            float wv[4][4];
#pragma unroll
            for (int e4 = 0; e4 < 4; e4++) {
                float4 wq = ws4[(eh * 4 + e4) * 256 + kidx];   // LDS.128, no conflicts
                wv[e4][0] = wq.x; wv[e4][1] = wq.y; wv[e4][2] = wq.z; wv[e4][3] = wq.w;
            }
#pragma unroll
            for (int e4 = 0; e4 < 4; e4++) {
                int e = eh * 4 + e4;
#pragma unroll
                for (int j = 0; j < 4; j++)
                    acc[0][e] = __fmaf_rn(hj0[j], wv[e4][j], acc[0][e]);
#pragma unroll
                for (int j = 0; j < 4; j++)
                    acc[1][e] = __fmaf_rn(hj1[j], wv[e4][j], acc[1][e]);
            }
        }
    }

    // 32-lane tree combine (pairing frozen)
#pragma unroll
    for (int off = 16; off > 0; off >>= 1)
#pragma unroll
        for (int t = 0; t < 2; t++)
#pragma unroll
            for (int e = 0; e < 8; e++)
                acc[t][e] = __fadd_rn(acc[t][e],
                                      __shfl_xor_sync(0xFFFFFFFFu, acc[t][e], off));

    if (lane < 2) {
        int tok = tok0 + lane;
        int b = tok >> 12;
        int s = tok & (SEQ - 1);

        float m = acc[lane][0];
#pragma unroll
        for (int e = 1; e < 8; e++) m = fmaxf(m, acc[lane][e]);

        float ex[8];
        float sum = 0.0f;
#pragma unroll
        for (int e = 0; e < 8; e++) {
            float d = __fsub_rn(acc[lane][e], m);
            ex[e] = expf(d);
            sum = __fadd_rn(sum, ex[e]);
        }
#pragma unroll
        for (int e = 0; e < 8; e++)
            g_aff[((size_t)(b * NEXP + e)) * SEQ + s] = __fdiv_rn(ex[e], sum);
    }
}

// ---------------------------------------------------------------------------
// Kernel B: per half-pair (2048 keys), 1024 threads: sort 4 chunks of 512
// descending, then bitonic top-k merge-selection 4 -> 2 -> 1; outputs ONE
// descending run of 512 = exact top-512 of the 2048 (distinct keys =>
// identical to full-sort prefix). Key = (float_bits<<32) | ~index.
// ---------------------------------------------------------------------------
__global__ __launch_bounds__(1024) void chunksort_kernel(void)
{
    __shared__ unsigned long long keys[2048];
    int pair = blockIdx.x >> 1;
    int half = blockIdx.x & 1;
    int gbase = half * 2048;
    const float* a = g_aff + (size_t)pair * SEQ + gbase;
    int tid = threadIdx.x;

    for (int t = tid; t < 2048; t += 1024) {
        unsigned int fb = __float_as_uint(a[t]);
        keys[t] = ((unsigned long long)fb << 32) | (unsigned int)(~(gbase + t));
    }
    __syncthreads();

    // Phase 1: sort each 512-chunk descending (1024 compares/stage, 1/thread)
    for (int k = 2; k <= 512; k <<= 1) {
        for (int j = k >> 1; j > 0; j >>= 1) {
            int c = tid;
            int t = ((c & ~(j - 1)) << 1) | (c & (j - 1));
            int txj = t | j;
            unsigned long long x = keys[t], y = keys[txj];
            bool desc = (((t & 511) & k) == 0);
            if (desc ? (x < y) : (x > y)) { keys[t] = y; keys[txj] = x; }
            __syncthreads();
        }
    }

    // Phase 2: merge-select (0,1)->run@0, (2,3)->run@1024, then 9 desc stages
    {
        int m = tid >> 9, i = tid & 511;
        int baseA = m * 1024, baseB = baseA + 512;
        unsigned long long x = keys[baseA + i], y = keys[baseB + (511 - i)];
        __syncthreads();                  // all reads before writes
        keys[baseA + i] = (x > y) ? x : y;
    }
    __syncthreads();
    for (int j = 256; j > 0; j >>= 1) {
        if (tid < 512) {
            int m = tid >> 8, i = tid & 255;
            int base = m * 1024;
            int t = base + (((i & ~(j - 1)) << 1) | (i & (j - 1)));
            int txj = t | j;
            unsigned long long x = keys[t], y = keys[txj];
            if (x < y) { keys[t] = y; keys[txj] = x; }
        }
        __syncthreads();
    }

    // Phase 3: merge-select (0, 1024) -> final top-512 @0, then 9 desc stages
    if (tid < 512) {
        unsigned long long x = keys[tid], y = keys[1024 + (511 - tid)];
        keys[tid] = (x > y) ? x : y;
    }
    __syncthreads();
    for (int j = 256; j > 0; j >>= 1) {
        if (tid < 256) {
            int t = ((tid & ~(j - 1)) << 1) | (tid & (j - 1));
            int txj = t | j;
            unsigned long long x = keys[t], y = keys[txj];
            if (x < y) { keys[t] = y; keys[txj] = x; }
        }
        __syncthreads();
    }

    if (tid < 512)
        g_runs[(size_t)pair * 1024 + half * 512 + tid] = keys[tid];
}

// ---------------------------------------------------------------------------
// Kernel C: per pair, merge-select the two 512-runs -> final top-512 desc,
// then fused epilogue (indices, scores, one-hot into pre-zeroed mask).
// ---------------------------------------------------------------------------
__global__ __launch_bounds__(512) void merge_epi_kernel(float* __restrict__ out)
{
    __shared__ unsigned long long keys[1024];
    int pair = blockIdx.x;
    int tid = threadIdx.x;
    const unsigned long long* src = g_runs + (size_t)pair * 1024;

    keys[tid] = src[tid];
    keys[tid + 512] = src[tid + 512];
    __syncthreads();

    unsigned long long x = keys[tid], y = keys[512 + (511 - tid)];
    keys[tid] = (x > y) ? x : y;
    __syncthreads();
    for (int j = 256; j > 0; j >>= 1) {
        if (tid < 256) {
            int t = ((tid & ~(j - 1)) << 1) | (tid & (j - 1));
            int txj = t | j;
            unsigned long long a = keys[t], b = keys[txj];
            if (a < b) { keys[t] = b; keys[txj] = a; }
        }
        __syncthreads();
    }

    unsigned long long key = keys[tid];
    int   si = (int)(~(unsigned int)key);
    float v  = __uint_as_float((unsigned int)(key >> 32));
    int row = pair * CAP + tid;
    out[IDX_OFF + row]   = (float)si;                 // topk_indices
    out[SCORE_OFF + row] = v;                         // topk_scores
    out[MASK_OFF + (size_t)row * SEQ + si] = 1.0f;    // one-hot
}

extern "C" void kernel_launch(void* const* d_in, const int* in_sizes, int n_in,
                              void* d_out, int out_size)
{
    const float* hid = (const float*)d_in[0];   // [8, 4096, 1024] fp32
    const float* w   = (const float*)d_in[1];   // [1024, 8] fp32
    float* out = (float*)d_out;

    gate_zf_kernel<<<GATE_BLOCKS + ZF_BLOCKS, 256>>>(hid, w, out);  // 6144
    chunksort_kernel<<<SORT_BLOCKS, 1024>>>();                       // 128
    merge_epi_kernel<<<NPAIR, 512>>>(out);                           // 64
}